// round 15
// baseline (speedup 1.0000x reference)
#include <cuda_runtime.h>
#include <cstdint>

#define BATCH    4194304u
#define EPT      2u                         // elements per thread
#define INV_LN2  1.4426950408889634f
// u = k*2^-23 exactly (k = bits>>9). Patch when k > 8382700 (u > ~0.99930), i.e.
// u > UPATCH with UPATCH = 8382700*2^-23 — exactly representable, so the float
// compare is bit-equivalent to the integer one but issues off the alu pipe.
#define UPATCH   0.99930715560913085938f    /* 8382700 * 2^-23, exact */

// Tables by (card*3+action): [0..5] lp = log_softmax(W.T+b); [6..11] wn = -exp(-lp)
// argmax_a lp_a - ln(-ln u_a)  ==  argmin_a  lg2(u_a) * wn_a   (exact monotone map)
// Init kernel writes through the constant symbol's device alias; const caches are
// invalidated per launch, so the stream-ordered sample kernel reads fresh values.
__constant__ float c_tbl[12];

__global__ void init_logp_kernel(const float* __restrict__ W,
                                 const float* __restrict__ bias,
                                 float* __restrict__ ctbl_alias) {
    int j = threadIdx.x;                    // one thread per (card, action) entry
    if (blockIdx.x == 0 && j < 6) {
        int c = j / 3, a = j % 3;
        // W is (3,2) row-major; x_i = W[i,c] + b[i]
        float x0 = W[0 * 2 + c] + bias[0];
        float x1 = W[1 * 2 + c] + bias[1];
        float x2 = W[2 * 2 + c] + bias[2];
        float m  = fmaxf(x0, fmaxf(x1, x2));
        float l  = logf(expf(x0 - m) + expf(x1 - m) + expf(x2 - m));
        float xa = (a == 0) ? x0 : (a == 1) ? x1 : x2;
        float lp = (xa - m) - l;
        ctbl_alias[j]     = lp;
        ctbl_alias[6 + j] = -expf(-lp);
    }
}

// JAX partitionable-threefry 32-bit draw for global element index i (< 2^32):
//   (o0, o1) = threefry2x32(key=(0,42), x0=hi32(i)=0, x1=lo32(i)=i); bits = o0 ^ o1
__device__ __forceinline__ uint32_t tf_bits(uint32_t ctr) {
    const uint32_t k1 = 42u;
    const uint32_t k2 = 42u ^ 0x1BD11BDAu;
    uint32_t x0 = 0u;            // hi32 + k0 = 0
    uint32_t x1 = ctr + 42u;
#define TF_RND(r) { x0 += x1; x1 = __funnelshift_l(x1, x1, (r)); x1 ^= x0; }
    TF_RND(13) TF_RND(15) TF_RND(26) TF_RND(6)
    x0 += k1; x1 += k2 + 1u;
    TF_RND(17) TF_RND(29) TF_RND(16) TF_RND(24)
    x0 += k2; x1 += 2u;
    TF_RND(13) TF_RND(15) TF_RND(26) TF_RND(6)
    x1 += k1 + 3u;               // x0 += k0 folds away
    TF_RND(17) TF_RND(29) TF_RND(16) TF_RND(24)
    x0 += k1; x1 += k2 + 4u;
    TF_RND(13) TF_RND(15) TF_RND(26) TF_RND(6)
    x0 += k2; x1 += 5u;
#undef TF_RND
    return x0 ^ x1;
}

__global__ void __launch_bounds__(256)
sample_kernel(const int* __restrict__ cards, float* __restrict__ out) {
    uint32_t e0 = (blockIdx.x * 256u + threadIdx.x) * EPT;  // grid divides exactly

    int2 cards2 = *reinterpret_cast<const int2*>(cards + e0);
    int  cardv[2] = {cards2.x, cards2.y};

    float2 u0d;
    float4 belq;
    float4 lcfq;
    float* u0p  = &u0d.x;
    float* belp = &belq.x;
    float* lcfp = &lcfq.x;

    #pragma unroll
    for (uint32_t e = 0; e < EPT; e++) {
        uint32_t base = (e0 + e) * 6u;

        // 6 independent threefry chains; uniform in one funnel-shift:
        // vb = (o>>9)|0x3f800000 ; u = as_float(vb) - 1 (exact).
        // Patch near-1 draws (float compare, == integer k > 8382700 exactly)
        // with precise log, then fold wn in. Only u[] and p[] stay live.
        float u[6], p[6];
        #pragma unroll
        for (int j = 0; j < 6; j++) {
            uint32_t o  = tf_bits(base + (uint32_t)j);
            uint32_t vb = __funnelshift_r(o, 0x7Fu, 9);
            u[j] = __uint_as_float(vb) - 1.0f;
            float L = __log2f(u[j]);               // MUFU.LG2, abs err ~2^-22
            if (u[j] > UPATCH) L = logf(u[j]) * INV_LN2;   // rare: P ~ 7e-4/draw
            p[j] = L * c_tbl[6 + j];               // positive; argmin == ref argmax
        }

        int   cf[2];
        float lcf[2];
        bool  need_exact = false;
        #pragma unroll
        for (int c = 0; c < 2; c++) {
            float p0 = p[c*3+0], p1 = p[c*3+1], p2 = p[c*3+2];
            int   bi = 0;
            float best = p0;
            if (p1 < best) { best = p1; bi = 1; }
            if (p2 < best) { best = p2; bi = 2; }
            float second = fmaxf(fminf(p0, p1), fminf(fmaxf(p0, p1), p2));
            // fast rel err <= ~2.4e-4; eps = 1e-3 (4x margin)
            need_exact |= (second < fmaf(best, 1e-3f, best));
            cf[c]  = bi;
            lcf[c] = c_tbl[c*3 + bi];
        }

        if (need_exact) {
            // Bit-exact reference arithmetic: s = lp - log(-log(max(u, tiny)))
            #pragma unroll
            for (int c = 0; c < 2; c++) {
                int   bi   = 0;
                float best = -1e30f;
                #pragma unroll
                for (int a = 0; a < 3; a++) {
                    float uc = fmaxf(u[c*3+a], 1.17549435e-38f);
                    float s  = c_tbl[c*3+a] - logf(-logf(uc));
                    if (s > best) { best = s; bi = a; }   // first-max tie rule
                }
                cf[c]  = bi;
                lcf[c] = c_tbl[c*3 + bi];
            }
        }

        int card = cardv[e];                       // in {0,1}
        int u0i  = (card == 0) ? cf[0] : cf[1];
        u0p[e]   = (float)u0i;

        bool eq = (cf[0] == cf[1]);
        belp[e*2 + 0] = eq ? 0.5f : ((card == 0) ? 1.0f : 0.0f);
        belp[e*2 + 1] = eq ? 0.5f : ((card == 0) ? 0.0f : 1.0f);
        lcfp[e*2 + 0] = lcf[0];
        lcfp[e*2 + 1] = lcf[1];
    }

    // Vectorized stores: out = [u0(B) | beliefs(B,2) | log_cf(B,2)]
    *reinterpret_cast<float2*>(out + e0)                          = u0d;
    *reinterpret_cast<float4*>(out + BATCH + 2u * e0)             = belq;
    *reinterpret_cast<float4*>(out + 3 * (size_t)BATCH + 2u * e0) = lcfq;
}

extern "C" void kernel_launch(void* const* d_in, const int* in_sizes, int n_in,
                              void* d_out, int out_size) {
    const int*   cards = (const int*)d_in[0];     // cards_0: (B,) int32
    const float* W     = (const float*)d_in[1];   // (3,2) float32
    const float* bias  = (const float*)d_in[2];   // (3,) float32
    float*       out   = (float*)d_out;           // [u0(B) | beliefs(B,2) | log_cf(B,2)]

    // Constant symbol's device alias (host-side query; capture-safe, no alloc).
    void* ctbl_alias = nullptr;
    cudaGetSymbolAddress(&ctbl_alias, c_tbl);

    init_logp_kernel<<<1, 32>>>(W, bias, (float*)ctbl_alias);
    sample_kernel<<<BATCH / (256 * EPT), 256>>>(cards, out);
}

// round 16
// speedup vs baseline: 1.0034x; 1.0034x over previous
#include <cuda_runtime.h>
#include <cstdint>

#define BATCH    4194304u
#define EPT      2u                         // elements per thread
#define INV_LN2  1.4426950408889634f
// vbits = (bits>>9)|0x3f800000 ; patch when u > ~0.99930 (MUFU.LG2 rel err blows up)
#define VPATCH   (0x3f800000u | 8382700u)

// JAX partitionable-threefry 32-bit draw for global element index i (< 2^32):
//   (o0, o1) = threefry2x32(key=(0,42), x0=hi32(i)=0, x1=lo32(i)=i); bits = o0 ^ o1
__device__ __forceinline__ uint32_t tf_bits(uint32_t ctr) {
    const uint32_t k1 = 42u;
    const uint32_t k2 = 42u ^ 0x1BD11BDAu;
    uint32_t x0 = 0u;            // hi32 + k0 = 0
    uint32_t x1 = ctr + 42u;
#define TF_RND(r) { x0 += x1; x1 = __funnelshift_l(x1, x1, (r)); x1 ^= x0; }
    TF_RND(13) TF_RND(15) TF_RND(26) TF_RND(6)
    x0 += k1; x1 += k2 + 1u;
    TF_RND(17) TF_RND(29) TF_RND(16) TF_RND(24)
    x0 += k2; x1 += 2u;
    TF_RND(13) TF_RND(15) TF_RND(26) TF_RND(6)
    x1 += k1 + 3u;               // x0 += k0 folds away
    TF_RND(17) TF_RND(29) TF_RND(16) TF_RND(24)
    x0 += k1; x1 += k2 + 4u;
    TF_RND(13) TF_RND(15) TF_RND(26) TF_RND(6)
    x0 += k2; x1 += 5u;
#undef TF_RND
    return x0 ^ x1;
}

// Single kernel: each block derives the tiny (2 cards x 3 actions) tables itself
// in smem, then samples. Tables by j = card*3+action:
//   s_tbl[j]   = lp_j  = log_softmax(W.T + b)        (output value)
//   s_tbl[6+j] = wn_j  = -exp(-lp_j)                 (argmin weight)
// argmax_a lp_a - ln(-ln u_a)  ==  argmin_a  lg2(u_a) * wn_a  (exact monotone map)
__global__ void __launch_bounds__(256)
sample_kernel(const int* __restrict__ cards,
              const float* __restrict__ W,
              const float* __restrict__ bias,
              float* __restrict__ out) {
    __shared__ float s_tbl[12];

    if (threadIdx.x < 6) {
        int j = threadIdx.x;
        int c = j / 3, a = j % 3;
        // W is (3,2) row-major; x_i = W[i,c] + b[i]
        float x0 = W[0 * 2 + c] + bias[0];
        float x1 = W[1 * 2 + c] + bias[1];
        float x2 = W[2 * 2 + c] + bias[2];
        float m  = fmaxf(x0, fmaxf(x1, x2));
        float l  = logf(expf(x0 - m) + expf(x1 - m) + expf(x2 - m));
        float xa = (a == 0) ? x0 : (a == 1) ? x1 : x2;
        float lp = (xa - m) - l;
        s_tbl[j]     = lp;
        s_tbl[6 + j] = -expf(-lp);
    }

    uint32_t e0 = (blockIdx.x * 256u + threadIdx.x) * EPT;  // grid divides exactly
    int2 cards2 = *reinterpret_cast<const int2*>(cards + e0);
    int  cardv[2] = {cards2.x, cards2.y};

    __syncthreads();
    float lp[6], wn[6];
    #pragma unroll
    for (int i = 0; i < 6; i++) { lp[i] = s_tbl[i]; wn[i] = s_tbl[6 + i]; }

    float2 u0d;
    float4 belq;
    float4 lcfq;
    float* u0p  = &u0d.x;
    float* belp = &belq.x;
    float* lcfp = &lcfq.x;

    #pragma unroll
    for (uint32_t e = 0; e < EPT; e++) {
        uint32_t base = (e0 + e) * 6u;

        // 6 independent threefry chains; uniform in one funnel-shift:
        // vb = (o>>9)|0x3f800000 ; u = as_float(vb) - 1 (exact).
        // Patch near-1 draws with precise log, then fold wn in.
        float u[6], p[6];
        #pragma unroll
        for (int j = 0; j < 6; j++) {
            uint32_t o  = tf_bits(base + (uint32_t)j);
            uint32_t vb = __funnelshift_r(o, 0x7Fu, 9);
            u[j] = __uint_as_float(vb) - 1.0f;
            float L = __log2f(u[j]);               // MUFU.LG2, abs err ~2^-22
            if (vb > VPATCH) L = logf(u[j]) * INV_LN2;   // rare: P ~ 7e-4/draw
            p[j] = L * wn[j];                      // positive; argmin == ref argmax
        }

        int   cf[2];
        float lcf[2];
        bool  need_exact = false;
        #pragma unroll
        for (int c = 0; c < 2; c++) {
            float p0 = p[c*3+0], p1 = p[c*3+1], p2 = p[c*3+2];
            int   bi = 0;
            float best = p0;
            if (p1 < best) { best = p1; bi = 1; }
            if (p2 < best) { best = p2; bi = 2; }
            float second = fmaxf(fminf(p0, p1), fminf(fmaxf(p0, p1), p2));
            // fast rel err <= ~2.4e-4; eps = 1e-3 (4x margin)
            need_exact |= (second < fmaf(best, 1e-3f, best));
            cf[c]  = bi;
            lcf[c] = lp[c*3 + bi];
        }

        if (need_exact) {
            // Bit-exact reference arithmetic: s = lp - log(-log(max(u, tiny)))
            #pragma unroll
            for (int c = 0; c < 2; c++) {
                int   bi   = 0;
                float best = -1e30f;
                #pragma unroll
                for (int a = 0; a < 3; a++) {
                    float uc = fmaxf(u[c*3+a], 1.17549435e-38f);
                    float s  = lp[c*3+a] - logf(-logf(uc));
                    if (s > best) { best = s; bi = a; }   // first-max tie rule
                }
                cf[c]  = bi;
                lcf[c] = lp[c*3 + bi];
            }
        }

        int card = cardv[e];                       // in {0,1}
        int u0i  = (card == 0) ? cf[0] : cf[1];
        u0p[e]   = (float)u0i;

        bool eq = (cf[0] == cf[1]);
        belp[e*2 + 0] = eq ? 0.5f : ((card == 0) ? 1.0f : 0.0f);
        belp[e*2 + 1] = eq ? 0.5f : ((card == 0) ? 0.0f : 1.0f);
        lcfp[e*2 + 0] = lcf[0];
        lcfp[e*2 + 1] = lcf[1];
    }

    // Vectorized stores: out = [u0(B) | beliefs(B,2) | log_cf(B,2)]
    *reinterpret_cast<float2*>(out + e0)                          = u0d;
    *reinterpret_cast<float4*>(out + BATCH + 2u * e0)             = belq;
    *reinterpret_cast<float4*>(out + 3 * (size_t)BATCH + 2u * e0) = lcfq;
}

extern "C" void kernel_launch(void* const* d_in, const int* in_sizes, int n_in,
                              void* d_out, int out_size) {
    const int*   cards = (const int*)d_in[0];     // cards_0: (B,) int32
    const float* W     = (const float*)d_in[1];   // (3,2) float32
    const float* bias  = (const float*)d_in[2];   // (3,) float32
    float*       out   = (float*)d_out;           // [u0(B) | beliefs(B,2) | log_cf(B,2)]

    sample_kernel<<<BATCH / (256 * EPT), 256>>>(cards, W, bias, out);
}

// round 17
// speedup vs baseline: 1.0080x; 1.0046x over previous
#include <cuda_runtime.h>
#include <cstdint>

#define BATCH    4194304u
#define EPT      2u                         // elements per thread
#define INV_LN2  1.4426950408889634f
// vbits = (bits>>9)|0x3f800000 ; patch when u > ~0.99930 (MUFU.LG2 rel err blows up)
#define VPATCH   (0x3f800000u | 8382700u)

// JAX partitionable-threefry 32-bit draw for global element index i (< 2^32):
//   (o0, o1) = threefry2x32(key=(0,42), x0=hi32(i)=0, x1=lo32(i)=i); bits = o0 ^ o1
__device__ __forceinline__ uint32_t tf_bits(uint32_t ctr) {
    const uint32_t k1 = 42u;
    const uint32_t k2 = 42u ^ 0x1BD11BDAu;
    uint32_t x0 = 0u;            // hi32 + k0 = 0
    uint32_t x1 = ctr + 42u;
#define TF_RND(r) { x0 += x1; x1 = __funnelshift_l(x1, x1, (r)); x1 ^= x0; }
    TF_RND(13) TF_RND(15) TF_RND(26) TF_RND(6)
    x0 += k1; x1 += k2 + 1u;
    TF_RND(17) TF_RND(29) TF_RND(16) TF_RND(24)
    x0 += k2; x1 += 2u;
    TF_RND(13) TF_RND(15) TF_RND(26) TF_RND(6)
    x1 += k1 + 3u;               // x0 += k0 folds away
    TF_RND(17) TF_RND(29) TF_RND(16) TF_RND(24)
    x0 += k1; x1 += k2 + 4u;
    TF_RND(13) TF_RND(15) TF_RND(26) TF_RND(6)
    x0 += k2; x1 += 5u;
#undef TF_RND
    return x0 ^ x1;
}

// Opaque shared load: ptxas cannot hoist/promote these into long-lived registers
// (that promotion cost 8 regs and 20% occupancy in the plain-smem variant).
__device__ __forceinline__ float lds_f32(uint32_t addr) {
    float v;
    asm volatile("ld.shared.f32 %0, [%1];" : "=f"(v) : "r"(addr));
    return v;
}

// Single kernel: each block derives the (2 cards x 3 actions) tables in smem,
// then samples, reading the table via broadcast LDS (LSU pipe, not the binding
// alu pipe). Table by j = card*3+action:
//   s_tbl[j]   = lp_j = log_softmax(W.T + b)   (output value)
//   s_tbl[6+j] = wn_j = -exp(-lp_j)            (argmin weight)
// argmax_a lp_a - ln(-ln u_a)  ==  argmin_a  lg2(u_a) * wn_a  (exact monotone map)
__global__ void __launch_bounds__(256)
sample_kernel(const int* __restrict__ cards,
              const float* __restrict__ W,
              const float* __restrict__ bias,
              float* __restrict__ out) {
    __shared__ float s_tbl[12];

    if (threadIdx.x < 6) {
        int j = threadIdx.x;
        int c = j / 3, a = j % 3;
        // W is (3,2) row-major; x_i = W[i,c] + b[i]
        float x0 = W[0 * 2 + c] + bias[0];
        float x1 = W[1 * 2 + c] + bias[1];
        float x2 = W[2 * 2 + c] + bias[2];
        float m  = fmaxf(x0, fmaxf(x1, x2));
        float l  = logf(expf(x0 - m) + expf(x1 - m) + expf(x2 - m));
        float xa = (a == 0) ? x0 : (a == 1) ? x1 : x2;
        float lp = (xa - m) - l;
        s_tbl[j]     = lp;
        s_tbl[6 + j] = -expf(-lp);
    }

    uint32_t e0 = (blockIdx.x * 256u + threadIdx.x) * EPT;  // grid divides exactly
    int2 cards2 = *reinterpret_cast<const int2*>(cards + e0);
    int  cardv[2] = {cards2.x, cards2.y};

    __syncthreads();
    uint32_t sb = (uint32_t)__cvta_generic_to_shared(s_tbl);

    float2 u0d;
    float4 belq;
    float4 lcfq;
    float* u0p  = &u0d.x;
    float* belp = &belq.x;
    float* lcfp = &lcfq.x;

    #pragma unroll
    for (uint32_t e = 0; e < EPT; e++) {
        uint32_t base = (e0 + e) * 6u;

        // 6 independent threefry chains; uniform in one funnel-shift:
        // vb = (o>>9)|0x3f800000 ; u = as_float(vb) - 1 (exact).
        // Patch near-1 draws with precise log, then fold wn in (LDS per use).
        float u[6], p[6];
        #pragma unroll
        for (int j = 0; j < 6; j++) {
            uint32_t o  = tf_bits(base + (uint32_t)j);
            uint32_t vb = __funnelshift_r(o, 0x7Fu, 9);
            u[j] = __uint_as_float(vb) - 1.0f;
            float L = __log2f(u[j]);               // MUFU.LG2, abs err ~2^-22
            if (vb > VPATCH) L = logf(u[j]) * INV_LN2;   // rare: P ~ 7e-4/draw
            p[j] = L * lds_f32(sb + (6 + j) * 4);  // positive; argmin == ref argmax
        }

        int   cf[2];
        float lcf[2];
        bool  need_exact = false;
        #pragma unroll
        for (int c = 0; c < 2; c++) {
            float p0 = p[c*3+0], p1 = p[c*3+1], p2 = p[c*3+2];
            int   bi = 0;
            float best = p0;
            if (p1 < best) { best = p1; bi = 1; }
            if (p2 < best) { best = p2; bi = 2; }
            float second = fmaxf(fminf(p0, p1), fminf(fmaxf(p0, p1), p2));
            // fast rel err <= ~2.4e-4; eps = 1e-3 (4x margin)
            need_exact |= (second < fmaf(best, 1e-3f, best));
            cf[c]  = bi;
            lcf[c] = lds_f32(sb + (uint32_t)(c * 3 + bi) * 4);   // dynamic-index LDS
        }

        if (need_exact) {
            // Bit-exact reference arithmetic: s = lp - log(-log(max(u, tiny)))
            #pragma unroll
            for (int c = 0; c < 2; c++) {
                int   bi   = 0;
                float best = -1e30f;
                #pragma unroll
                for (int a = 0; a < 3; a++) {
                    float uc = fmaxf(u[c*3+a], 1.17549435e-38f);
                    float s  = lds_f32(sb + (uint32_t)(c*3+a) * 4) - logf(-logf(uc));
                    if (s > best) { best = s; bi = a; }   // first-max tie rule
                }
                cf[c]  = bi;
                lcf[c] = lds_f32(sb + (uint32_t)(c * 3 + bi) * 4);
            }
        }

        int card = cardv[e];                       // in {0,1}
        int u0i  = (card == 0) ? cf[0] : cf[1];
        u0p[e]   = (float)u0i;

        bool eq = (cf[0] == cf[1]);
        belp[e*2 + 0] = eq ? 0.5f : ((card == 0) ? 1.0f : 0.0f);
        belp[e*2 + 1] = eq ? 0.5f : ((card == 0) ? 0.0f : 1.0f);
        lcfp[e*2 + 0] = lcf[0];
        lcfp[e*2 + 1] = lcf[1];
    }

    // Vectorized stores: out = [u0(B) | beliefs(B,2) | log_cf(B,2)]
    *reinterpret_cast<float2*>(out + e0)                          = u0d;
    *reinterpret_cast<float4*>(out + BATCH + 2u * e0)             = belq;
    *reinterpret_cast<float4*>(out + 3 * (size_t)BATCH + 2u * e0) = lcfq;
}

extern "C" void kernel_launch(void* const* d_in, const int* in_sizes, int n_in,
                              void* d_out, int out_size) {
    const int*   cards = (const int*)d_in[0];     // cards_0: (B,) int32
    const float* W     = (const float*)d_in[1];   // (3,2) float32
    const float* bias  = (const float*)d_in[2];   // (3,) float32
    float*       out   = (float*)d_out;           // [u0(B) | beliefs(B,2) | log_cf(B,2)]

    sample_kernel<<<BATCH / (256 * EPT), 256>>>(cards, W, bias, out);
}